// round 1
// baseline (speedup 1.0000x reference)
#include <cuda_runtime.h>
#include <math.h>
#include <stdint.h>

// Problem constants
#define IN_DIM  2048
#define HID     1024
#define ATT_NUM 40
#define BATCH   4096

// Tiling
#define BM 128
#define BN 128
#define BK 16
#define NIT (IN_DIM / BK)      // 128 K-iterations
#define NTILES (HID / BN)      // 8 column tiles per head

// Padded smem widths (chosen so fragment loads are bank-conflict-free:
//  A: width 20 -> bank = (20r + c) % 32, rows 0..7 x cols t,t+4 all distinct
//  B: width 136 -> bank = (8r + c) % 32, rows t,t+4 x cols g all distinct)
#define AW (BK + 4)            // 20
#define BW (BN + 8)            // 136

// Deterministic partial-sum scratch: y_part[b][a][ntile]
__device__ float y_part[BATCH * ATT_NUM * NTILES];

__device__ __forceinline__ uint32_t f2tf32(float x) {
    uint32_t u;
    asm("cvt.rna.tf32.f32 %0, %1;" : "=r"(u) : "f"(x));
    return u;
}

__device__ __forceinline__ void mma_tf32(float* c, const uint32_t* a, const uint32_t* b) {
    asm volatile(
        "mma.sync.aligned.m16n8k8.row.col.f32.tf32.tf32.f32 "
        "{%0,%1,%2,%3}, {%4,%5,%6,%7}, {%8,%9}, {%0,%1,%2,%3};\n"
        : "+f"(c[0]), "+f"(c[1]), "+f"(c[2]), "+f"(c[3])
        : "r"(a[0]), "r"(a[1]), "r"(a[2]), "r"(a[3]), "r"(b[0]), "r"(b[1]));
}

__global__ __launch_bounds__(256, 2) void fused_head_gemm(
    const float* __restrict__ x,    // [4096, 2048]
    const float* __restrict__ W1,   // [40, 2048, 1024]
    const float* __restrict__ b1,   // [40, 1024]
    const float* __restrict__ W2)   // [40, 1024]
{
    __shared__ __align__(16) uint32_t As[2][BM][AW];
    __shared__ __align__(16) uint32_t Bs[2][BK][BW];
    __shared__ float b1s[BN], W2s[BN];
    __shared__ float red[BM][2];

    const int tid  = threadIdx.x;
    const int lane = tid & 31;
    const int wid  = tid >> 5;
    const int g = lane >> 2;       // group id 0..7
    const int t = lane & 3;        // thread-in-group 0..3
    const int warp_m = wid >> 1;   // 0..3 (M direction)
    const int warp_n = wid & 1;    // 0..1 (N direction)

    const int row0 = blockIdx.x * BM;     // batch row tile
    const int n0   = blockIdx.y * BN;     // hid column tile within head
    const int a    = blockIdx.z;          // head

    const float* W1a = W1 + (size_t)a * IN_DIM * HID;

    if (tid < BN) {
        b1s[tid] = b1[a * HID + n0 + tid];
        W2s[tid] = W2[a * HID + n0 + tid];
    }

    // Per-iteration load geometry:
    //  A: 128 rows x 16 cols = 512 float4; thread handles id = tid + j*256, j=0..1
    //     rowA = id>>2, colA4 = id&3
    //  B: 16 rows x 128 cols = 512 float4; rowB = id>>5, colB4 = id&31
    float4 ra[2], rb[2];

    // ---- Prologue: load k-iter 0 into buffer 0 ----
    {
        #pragma unroll
        for (int j = 0; j < 2; j++) {
            int id = tid + j * 256;
            ra[j] = *(const float4*)(x + (size_t)(row0 + (id >> 2)) * IN_DIM + ((id & 3) << 2));
            rb[j] = *(const float4*)(W1a + (size_t)(id >> 5) * HID + n0 + ((id & 31) << 2));
        }
        #pragma unroll
        for (int j = 0; j < 2; j++) {
            int id = tid + j * 256;
            int rA = id >> 2, cA = (id & 3) << 2;
            uint4 pa = make_uint4(f2tf32(ra[j].x), f2tf32(ra[j].y), f2tf32(ra[j].z), f2tf32(ra[j].w));
            *(uint4*)&As[0][rA][cA] = pa;
            int rB = id >> 5, cB = (id & 31) << 2;
            uint4 pb = make_uint4(f2tf32(rb[j].x), f2tf32(rb[j].y), f2tf32(rb[j].z), f2tf32(rb[j].w));
            *(uint4*)&Bs[0][rB][cB] = pb;
        }
    }
    __syncthreads();

    float acc[2][8][4];
    #pragma unroll
    for (int mt = 0; mt < 2; mt++)
        #pragma unroll
        for (int nt = 0; nt < 8; nt++)
            #pragma unroll
            for (int r = 0; r < 4; r++)
                acc[mt][nt][r] = 0.0f;

    int buf = 0;
    for (int it = 0; it < NIT; ++it) {
        // Prefetch next K-slab to registers (overlaps with mma below)
        if (it + 1 < NIT) {
            int k0 = (it + 1) * BK;
            #pragma unroll
            for (int j = 0; j < 2; j++) {
                int id = tid + j * 256;
                ra[j] = *(const float4*)(x + (size_t)(row0 + (id >> 2)) * IN_DIM + k0 + ((id & 3) << 2));
                rb[j] = *(const float4*)(W1a + (size_t)(k0 + (id >> 5)) * HID + n0 + ((id & 31) << 2));
            }
        }

        // Compute on current buffer: 2 k-steps of 8
        #pragma unroll
        for (int kk = 0; kk < BK / 8; ++kk) {
            uint32_t afr[2][4], bfr[8][2];
            #pragma unroll
            for (int mt = 0; mt < 2; mt++) {
                int r = warp_m * 32 + mt * 16 + g;
                afr[mt][0] = As[buf][r    ][kk * 8 + t];
                afr[mt][1] = As[buf][r + 8][kk * 8 + t];
                afr[mt][2] = As[buf][r    ][kk * 8 + t + 4];
                afr[mt][3] = As[buf][r + 8][kk * 8 + t + 4];
            }
            #pragma unroll
            for (int nt = 0; nt < 8; nt++) {
                int c = warp_n * 64 + nt * 8 + g;
                bfr[nt][0] = Bs[buf][kk * 8 + t    ][c];
                bfr[nt][1] = Bs[buf][kk * 8 + t + 4][c];
            }
            #pragma unroll
            for (int mt = 0; mt < 2; mt++)
                #pragma unroll
                for (int nt = 0; nt < 8; nt++)
                    mma_tf32(acc[mt][nt], afr[mt], bfr[nt]);
        }

        if (it + 1 < NIT) {
            __syncthreads();  // everyone done reading buf^1 from previous round
            #pragma unroll
            for (int j = 0; j < 2; j++) {
                int id = tid + j * 256;
                int rA = id >> 2, cA = (id & 3) << 2;
                uint4 pa = make_uint4(f2tf32(ra[j].x), f2tf32(ra[j].y), f2tf32(ra[j].z), f2tf32(ra[j].w));
                *(uint4*)&As[buf ^ 1][rA][cA] = pa;
                int rB = id >> 5, cB = (id & 31) << 2;
                uint4 pb = make_uint4(f2tf32(rb[j].x), f2tf32(rb[j].y), f2tf32(rb[j].z), f2tf32(rb[j].w));
                *(uint4*)&Bs[buf ^ 1][rB][cB] = pb;
            }
            __syncthreads();
            buf ^= 1;
        }
    }

    // ---- Epilogue: bias + exact gelu + dot with W2, reduce over columns ----
    // acc reg map (m16n8k8): c0=(g,2t) c1=(g,2t+1) c2=(g+8,2t) c3=(g+8,2t+1)
    float p[4] = {0.f, 0.f, 0.f, 0.f};   // rows: warp_m*32 + mt*16 + {g, g+8}
    #pragma unroll
    for (int mt = 0; mt < 2; mt++) {
        #pragma unroll
        for (int nt = 0; nt < 8; nt++) {
            int cbase = warp_n * 64 + nt * 8 + 2 * t;
            #pragma unroll
            for (int cc = 0; cc < 2; cc++) {
                int col = cbase + cc;
                float bb = b1s[col];
                float w2 = W2s[col];
                float v0 = acc[mt][nt][cc]     + bb;   // row g
                float v1 = acc[mt][nt][cc + 2] + bb;   // row g+8
                float h0 = 0.5f * v0 * (1.0f + erff(v0 * 0.70710678118654752f));
                float h1 = 0.5f * v1 * (1.0f + erff(v1 * 0.70710678118654752f));
                p[mt * 2 + 0] += h0 * w2;
                p[mt * 2 + 1] += h1 * w2;
            }
        }
    }
    // Reduce across the quad (lanes sharing a row: t = 0..3)
    #pragma unroll
    for (int s = 0; s < 4; s++) {
        p[s] += __shfl_xor_sync(0xffffffffu, p[s], 1);
        p[s] += __shfl_xor_sync(0xffffffffu, p[s], 2);
    }
    if (t == 0) {
        #pragma unroll
        for (int s = 0; s < 4; s++) {
            int r = warp_m * 32 + (s >> 1) * 16 + (s & 1) * 8 + g;
            red[r][warp_n] = p[s];
        }
    }
    __syncthreads();
    if (tid < BM) {
        float sum = red[tid][0] + red[tid][1];
        y_part[((size_t)(row0 + tid) * ATT_NUM + a) * NTILES + blockIdx.y] = sum;
    }
}

__global__ void finalize_kernel(const float* __restrict__ b2, float* __restrict__ out) {
    int i = blockIdx.x * blockDim.x + threadIdx.x;
    if (i >= BATCH * ATT_NUM) return;
    int a = i % ATT_NUM;
    float s = 0.0f;
    #pragma unroll
    for (int j = 0; j < NTILES; j++) s += y_part[(size_t)i * NTILES + j];
    s += b2[a];
    out[i] = 1.0f / (1.0f + expf(-s));
}

extern "C" void kernel_launch(void* const* d_in, const int* in_sizes, int n_in,
                              void* d_out, int out_size) {
    const float* x  = (const float*)d_in[0];
    const float* W1 = (const float*)d_in[1];
    const float* b1 = (const float*)d_in[2];
    const float* W2 = (const float*)d_in[3];
    const float* b2 = (const float*)d_in[4];
    float* out = (float*)d_out;

    dim3 grid(BATCH / BM, NTILES, ATT_NUM);  // (32, 8, 40), x fastest -> W1 strip reuse in-wave
    fused_head_gemm<<<grid, 256>>>(x, W1, b1, W2);

    int n = BATCH * ATT_NUM;
    finalize_kernel<<<(n + 255) / 256, 256>>>(b2, out);
}

// round 3
// speedup vs baseline: 2.6008x; 2.6008x over previous
#include <cuda_runtime.h>
#include <cuda_bf16.h>
#include <math.h>
#include <stdint.h>

#define IN_DIM  2048
#define HID     1024
#define ATT_NUM 40
#define BATCH   4096

#define BM 128
#define BN 256
#define KC 64               // K chunk: 64 bf16 = 128B rows (SW128 atom)
#define NC (IN_DIM / KC)    // 32
#define NSTG 3
#define NTILES (HID / BN)   // 4

// dynamic smem layout
#define OFF_B1S  0                       // 256 floats
#define OFF_W2S  1024                    // 256 floats
#define OFF_RED  2048                    // 128*4 floats
#define OFF_TILES 4096
#define STAGE_BYTES 49152                // A 16KB + B 32KB
#define A_OFF(s) (OFF_TILES + (s) * STAGE_BYTES)
#define B_OFF(s) (A_OFF(s) + 16384)
#define SMEM_TOTAL (OFF_TILES + NSTG * STAGE_BYTES)   // 151552

// static device scratch
__device__ __nv_bfloat16 g_xb[(size_t)BATCH * IN_DIM];            // 16 MB
__device__ __nv_bfloat16 g_w1t[(size_t)ATT_NUM * HID * IN_DIM];   // 168 MB [a][n][k]
__device__ float g_ypart[(size_t)BATCH * ATT_NUM * NTILES];

__device__ __forceinline__ uint32_t smem_u32(const void* p) {
    uint32_t a;
    asm("{ .reg .u64 t; cvta.to.shared.u64 t, %1; cvt.u32.u64 %0, t; }" : "=r"(a) : "l"(p));
    return a;
}
__device__ __forceinline__ void cp16(uint32_t dst, const void* src) {
    asm volatile("cp.async.cg.shared.global [%0], [%1], 16;" :: "r"(dst), "l"(src));
}
#define CP_COMMIT() asm volatile("cp.async.commit_group;" ::: "memory")
#define CP_WAIT(n)  asm volatile("cp.async.wait_group %0;" :: "n"(n) : "memory")

__device__ __forceinline__ void ldsm4(uint32_t* r, uint32_t addr) {
    asm volatile("ldmatrix.sync.aligned.m8n8.x4.shared.b16 {%0,%1,%2,%3}, [%4];"
                 : "=r"(r[0]), "=r"(r[1]), "=r"(r[2]), "=r"(r[3]) : "r"(addr));
}
__device__ __forceinline__ void mma16816(float* c, const uint32_t* a, uint32_t b0, uint32_t b1) {
    asm volatile(
        "mma.sync.aligned.m16n8k16.row.col.f32.bf16.bf16.f32 "
        "{%0,%1,%2,%3}, {%4,%5,%6,%7}, {%8,%9}, {%0,%1,%2,%3};\n"
        : "+f"(c[0]), "+f"(c[1]), "+f"(c[2]), "+f"(c[3])
        : "r"(a[0]), "r"(a[1]), "r"(a[2]), "r"(a[3]), "r"(b0), "r"(b1));
}

// ===== prepass: x -> bf16 =====
__global__ void convert_x_kernel(const float* __restrict__ x) {
    int i = blockIdx.x * blockDim.x + threadIdx.x;
    float4 v = reinterpret_cast<const float4*>(x)[i];
    __nv_bfloat162 lo = __floats2bfloat162_rn(v.x, v.y);
    __nv_bfloat162 hi = __floats2bfloat162_rn(v.z, v.w);
    uint2 u;
    u.x = *reinterpret_cast<uint32_t*>(&lo);
    u.y = *reinterpret_cast<uint32_t*>(&hi);
    reinterpret_cast<uint2*>(g_xb)[i] = u;
}

// ===== prepass: W1 [a][k][n] fp32 -> g_w1t [a][n][k] bf16 =====
__global__ void convert_w1_kernel(const float* __restrict__ W1) {
    __shared__ float t[32][33];
    int a  = blockIdx.z;
    int k0 = blockIdx.x * 32;
    int n0 = blockIdx.y * 32;
    int tx = threadIdx.x, ty = threadIdx.y;
    const float* src = W1 + (size_t)a * IN_DIM * HID + (size_t)k0 * HID + n0;
    #pragma unroll
    for (int j = 0; j < 4; j++)
        t[ty + j * 8][tx] = src[(size_t)(ty + j * 8) * HID + tx];
    __syncthreads();
    __nv_bfloat16* dst = g_w1t + (size_t)a * HID * IN_DIM + (size_t)n0 * IN_DIM + k0;
    #pragma unroll
    for (int j = 0; j < 4; j++)
        dst[(size_t)(ty + j * 8) * IN_DIM + tx] = __float2bfloat16(t[tx][ty + j * 8]);
}

// ===== fused GEMM + bias + gelu + W2-dot =====
extern __shared__ __align__(1024) char dynsmem[];

__device__ __forceinline__ void load_chunk(uint32_t smem_base, int kc, int s,
                                           const __nv_bfloat16* xA, const __nv_bfloat16* wB,
                                           int tid) {
    const __nv_bfloat16* xk = xA + kc * KC;
    const __nv_bfloat16* wk = wB + kc * KC;
    uint32_t ab = smem_base + A_OFF(s);
    uint32_t bb = smem_base + B_OFF(s);
    // A: 128 rows x 8 chunks = 1024 cp16; B: 256 rows x 8 = 2048; 256 threads
    #pragma unroll
    for (int i = 0; i < 4; i++) {
        int o = tid + i * 256;
        int row = o >> 3, j = o & 7;
        uint32_t bo = (row << 7) + (j << 4);
        uint32_t sw = bo ^ ((bo >> 3) & 0x70);
        cp16(ab + sw, xk + (size_t)row * IN_DIM + j * 8);
    }
    #pragma unroll
    for (int i = 0; i < 8; i++) {
        int o = tid + i * 256;
        int row = o >> 3, j = o & 7;
        uint32_t bo = (row << 7) + (j << 4);
        uint32_t sw = bo ^ ((bo >> 3) & 0x70);
        cp16(bb + sw, wk + (size_t)row * IN_DIM + j * 8);
    }
}

__global__ __launch_bounds__(256, 1)
void fused_head_gemm(const float* __restrict__ b1, const float* __restrict__ W2) {
    uint32_t smem_base = smem_u32(dynsmem);
    const int tid  = threadIdx.x;
    const int wid  = tid >> 5;
    const int lane = tid & 31;
    const int warp_m = wid & 1;     // 2 warps in M (64 rows each)
    const int warp_n = wid >> 1;    // 4 warps in N (64 cols each)
    const int g = lane >> 2;
    const int t = lane & 3;

    const int m0 = blockIdx.x * BM;
    const int n0 = blockIdx.y * BN;
    const int a  = blockIdx.z;

    const __nv_bfloat16* xA = g_xb  + (size_t)m0 * IN_DIM;
    const __nv_bfloat16* wB = g_w1t + (size_t)a * HID * IN_DIM + (size_t)n0 * IN_DIM;

    {   // bias / W2 tile to smem
        float* b1s = (float*)(dynsmem + OFF_B1S);
        float* w2s = (float*)(dynsmem + OFF_W2S);
        b1s[tid] = b1[a * HID + n0 + tid];
        w2s[tid] = W2[a * HID + n0 + tid];
    }

    // ---- per-lane ldmatrix base addresses ----
    // A frag fm: rows warp_m*64 + fm*16 + (lane&15); chunk = ks*2 + (lane>>4)
    // B frag pair p: nrows warp_n*64 + p*16 + (lane>>4)*8 + (lane&7); chunk = ks*2 + ((lane>>3)&1)
    uint32_t a_rowaddr[4], b_rowaddr[4];
    const int arow = (lane & 15);
    const int ahi  = lane >> 4;
    const int asw  = arow & 7;
    const int brow = ((lane >> 4) << 3) + (lane & 7);
    const int bhi  = (lane >> 3) & 1;
    const int bsw  = brow & 7;
    #pragma unroll
    for (int fm = 0; fm < 4; fm++)
        a_rowaddr[fm] = (uint32_t)((warp_m * 64 + fm * 16 + arow) << 7);
    #pragma unroll
    for (int p = 0; p < 4; p++)
        b_rowaddr[p] = (uint32_t)((warp_n * 64 + p * 16 + brow) << 7);

    float acc[4][8][4];
    #pragma unroll
    for (int fm = 0; fm < 4; fm++)
        #pragma unroll
        for (int fn = 0; fn < 8; fn++)
            #pragma unroll
            for (int r = 0; r < 4; r++) acc[fm][fn][r] = 0.0f;

    // prologue: stages 0,1
    #pragma unroll
    for (int s = 0; s < NSTG - 1; s++) {
        load_chunk(smem_base, s, s, xA, wB, tid);
        CP_COMMIT();
    }

    for (int kc = 0; kc < NC; ++kc) {
        if (kc == NC - 1) { CP_WAIT(0); } else { CP_WAIT(1); }
        __syncthreads();
        if (kc + 2 < NC) {
            load_chunk(smem_base, kc + 2, (kc + 2) % NSTG, xA, wB, tid);
            CP_COMMIT();
        }
        const uint32_t abase = smem_base + A_OFF(kc % NSTG);
        const uint32_t bbase = smem_base + B_OFF(kc % NSTG);

        #pragma unroll
        for (int ks = 0; ks < 4; ks++) {
            uint32_t Af[4][4], Bf[4][4];
            #pragma unroll
            for (int fm = 0; fm < 4; fm++) {
                uint32_t addr = abase + a_rowaddr[fm] + ((((ks * 2 + ahi) ^ asw)) << 4);
                ldsm4(Af[fm], addr);
            }
            #pragma unroll
            for (int p = 0; p < 4; p++) {
                uint32_t addr = bbase + b_rowaddr[p] + ((((ks * 2 + bhi) ^ bsw)) << 4);
                ldsm4(Bf[p], addr);
            }
            #pragma unroll
            for (int fm = 0; fm < 4; fm++)
                #pragma unroll
                for (int p = 0; p < 4; p++) {
                    mma16816(acc[fm][2 * p],     Af[fm], Bf[p][0], Bf[p][1]);
                    mma16816(acc[fm][2 * p + 1], Af[fm], Bf[p][2], Bf[p][3]);
                }
        }
    }

    // ---- epilogue ----
    const float* b1s = (const float*)(dynsmem + OFF_B1S);
    const float* w2s = (const float*)(dynsmem + OFF_W2S);
    float* red = (float*)(dynsmem + OFF_RED);   // [128][4]

    float pr[8];   // [fm][half]
    #pragma unroll
    for (int i = 0; i < 8; i++) pr[i] = 0.0f;

    #pragma unroll
    for (int fm = 0; fm < 4; fm++) {
        #pragma unroll
        for (int fn = 0; fn < 8; fn++) {
            int cbase = warp_n * 64 + fn * 8 + 2 * t;
            #pragma unroll
            for (int cc = 0; cc < 2; cc++) {
                int col = cbase + cc;
                float bb = b1s[col];
                float w2 = w2s[col];
                float v0 = acc[fm][fn][cc]     + bb;   // row g
                float v1 = acc[fm][fn][cc + 2] + bb;   // row g+8
                float h0 = 0.5f * v0 * (1.0f + erff(v0 * 0.70710678118654752f));
                float h1 = 0.5f * v1 * (1.0f + erff(v1 * 0.70710678118654752f));
                pr[fm * 2 + 0] += h0 * w2;
                pr[fm * 2 + 1] += h1 * w2;
            }
        }
    }
    #pragma unroll
    for (int i = 0; i < 8; i++) {
        pr[i] += __shfl_xor_sync(0xffffffffu, pr[i], 1);
        pr[i] += __shfl_xor_sync(0xffffffffu, pr[i], 2);
    }
    __syncthreads();   // done reading smem tiles; red aliases nothing anyway
    if (t == 0) {
        #pragma unroll
        for (int i = 0; i < 8; i++) {
            int row = warp_m * 64 + (i >> 1) * 16 + (i & 1) * 8 + g;
            red[row * 4 + warp_n] = pr[i];
        }
    }
    __syncthreads();
    if (tid < BM) {
        float sum = red[tid * 4 + 0] + red[tid * 4 + 1] + red[tid * 4 + 2] + red[tid * 4 + 3];
        g_ypart[((size_t)(m0 + tid) * ATT_NUM + a) * NTILES + blockIdx.y] = sum;
    }
}

__global__ void finalize_kernel(const float* __restrict__ b2, float* __restrict__ out) {
    int i = blockIdx.x * blockDim.x + threadIdx.x;
    if (i >= BATCH * ATT_NUM) return;
    int a = i % ATT_NUM;
    float s = 0.0f;
    #pragma unroll
    for (int j = 0; j < NTILES; j++) s += g_ypart[(size_t)i * NTILES + j];
    s += b2[a];
    out[i] = 1.0f / (1.0f + expf(-s));
}

extern "C" void kernel_launch(void* const* d_in, const int* in_sizes, int n_in,
                              void* d_out, int out_size) {
    const float* x  = (const float*)d_in[0];
    const float* W1 = (const float*)d_in[1];
    const float* b1 = (const float*)d_in[2];
    const float* W2 = (const float*)d_in[3];
    const float* b2 = (const float*)d_in[4];
    float* out = (float*)d_out;

    cudaFuncSetAttribute(fused_head_gemm, cudaFuncAttributeMaxDynamicSharedMemorySize, SMEM_TOTAL);

    convert_x_kernel<<<(BATCH * IN_DIM / 4) / 256, 256>>>(x);
    convert_w1_kernel<<<dim3(IN_DIM / 32, HID / 32, ATT_NUM), dim3(32, 8)>>>(W1);

    dim3 grid(BATCH / BM, HID / BN, ATT_NUM);   // (32, 4, 40); x fastest -> W1 strip reuse in-wave
    fused_head_gemm<<<grid, 256, SMEM_TOTAL>>>(b1, W2);

    int n = BATCH * ATT_NUM;
    finalize_kernel<<<(n + 255) / 256, 256>>>(b2, out);
}

// round 4
// speedup vs baseline: 2.9471x; 1.1331x over previous
#include <cuda_runtime.h>
#include <cuda_bf16.h>
#include <math.h>
#include <stdint.h>

#define IN_DIM  2048
#define HID     1024
#define ATT_NUM 40
#define BATCH   4096

#define BM 128
#define BN 256
#define KC 64               // K chunk: 64 rows of B, 128B A rows
#define NC (IN_DIM / KC)    // 32
#define NSTG 3
#define NTILES (HID / BN)   // 4

// dynamic smem layout
#define OFF_B1S  0
#define OFF_W2S  1024
#define OFF_RED  2048
#define OFF_TILES 4096
#define STAGE_BYTES 49152                // A 16KB ([128][128B] SW128) + B 32KB ([64][512B])
#define A_OFF(s) (OFF_TILES + (s) * STAGE_BYTES)
#define B_OFF(s) (A_OFF(s) + 16384)
#define SMEM_TOTAL (OFF_TILES + NSTG * STAGE_BYTES)   // 151552

// static device scratch
__device__ __nv_bfloat16 g_xb[(size_t)BATCH * IN_DIM];             // 16 MB [b][k]
__device__ __nv_bfloat16 g_w1b[(size_t)ATT_NUM * IN_DIM * HID];    // 168 MB [a][k][n] (native layout)
__device__ float g_ypart[(size_t)BATCH * ATT_NUM * NTILES];

__device__ __forceinline__ uint32_t smem_u32(const void* p) {
    uint32_t a;
    asm("{ .reg .u64 t; cvta.to.shared.u64 t, %1; cvt.u32.u64 %0, t; }" : "=r"(a) : "l"(p));
    return a;
}
__device__ __forceinline__ void cp16(uint32_t dst, const void* src) {
    asm volatile("cp.async.cg.shared.global [%0], [%1], 16;" :: "r"(dst), "l"(src));
}
#define CP_COMMIT() asm volatile("cp.async.commit_group;" ::: "memory")
#define CP_WAIT(n)  asm volatile("cp.async.wait_group %0;" :: "n"(n) : "memory")

__device__ __forceinline__ void ldsm4(uint32_t* r, uint32_t addr) {
    asm volatile("ldmatrix.sync.aligned.m8n8.x4.shared.b16 {%0,%1,%2,%3}, [%4];"
                 : "=r"(r[0]), "=r"(r[1]), "=r"(r[2]), "=r"(r[3]) : "r"(addr));
}
__device__ __forceinline__ void ldsm4t(uint32_t* r, uint32_t addr) {
    asm volatile("ldmatrix.sync.aligned.m8n8.x4.trans.shared.b16 {%0,%1,%2,%3}, [%4];"
                 : "=r"(r[0]), "=r"(r[1]), "=r"(r[2]), "=r"(r[3]) : "r"(addr));
}
__device__ __forceinline__ void mma16816(float* c, const uint32_t* a, uint32_t b0, uint32_t b1) {
    asm volatile(
        "mma.sync.aligned.m16n8k16.row.col.f32.bf16.bf16.f32 "
        "{%0,%1,%2,%3}, {%4,%5,%6,%7}, {%8,%9}, {%0,%1,%2,%3};\n"
        : "+f"(c[0]), "+f"(c[1]), "+f"(c[2]), "+f"(c[3])
        : "r"(a[0]), "r"(a[1]), "r"(a[2]), "r"(a[3]), "r"(b0), "r"(b1));
}

// ===== prepass: streaming fp32 -> bf16 =====
__global__ void convert_x_kernel(const float* __restrict__ x) {
    int i = blockIdx.x * blockDim.x + threadIdx.x;
    float4 v = reinterpret_cast<const float4*>(x)[i];
    __nv_bfloat162 lo = __floats2bfloat162_rn(v.x, v.y);
    __nv_bfloat162 hi = __floats2bfloat162_rn(v.z, v.w);
    uint2 u;
    u.x = *reinterpret_cast<uint32_t*>(&lo);
    u.y = *reinterpret_cast<uint32_t*>(&hi);
    reinterpret_cast<uint2*>(g_xb)[i] = u;
}
__global__ void convert_w1_kernel(const float* __restrict__ W1) {
    size_t i = (size_t)blockIdx.x * blockDim.x + threadIdx.x;
    float4 v = reinterpret_cast<const float4*>(W1)[i];
    __nv_bfloat162 lo = __floats2bfloat162_rn(v.x, v.y);
    __nv_bfloat162 hi = __floats2bfloat162_rn(v.z, v.w);
    uint2 u;
    u.x = *reinterpret_cast<uint32_t*>(&lo);
    u.y = *reinterpret_cast<uint32_t*>(&hi);
    reinterpret_cast<uint2*>(g_w1b)[i] = u;
}

// ===== fused GEMM + bias + gelu + W2-dot =====
extern __shared__ __align__(1024) char dynsmem[];

// One quarter of a chunk's loads (A: 1 cp16/thread, B: 2 cp16/thread).
__device__ __forceinline__ void load_part(uint32_t smem_base, int kc, int s, int part,
                                          const __nv_bfloat16* xA, const __nv_bfloat16* wB,
                                          int tid) {
    uint32_t ab = smem_base + A_OFF(s);
    uint32_t bb = smem_base + B_OFF(s);
    const __nv_bfloat16* xk = xA + kc * KC;
    const __nv_bfloat16* wk = wB + (size_t)(kc * KC) * HID;   // [k][n], n contiguous
    {
        int o = tid + part * 256;
        int row = o >> 3, j = o & 7;
        uint32_t bo = (uint32_t)((row << 7) | (j << 4));
        uint32_t sw = bo ^ ((bo >> 3) & 0x70);
        cp16(ab + sw, xk + (size_t)row * IN_DIM + j * 8);
    }
    #pragma unroll
    for (int h = 0; h < 2; h++) {
        int o = tid + (part * 2 + h) * 256;
        int krow = o >> 5, c = o & 31;                        // 64 k-rows x 32 chunks of 16B
        uint32_t sw = (uint32_t)(krow * 512) + (uint32_t)((c ^ (krow & 7)) << 4);
        cp16(bb + sw, wk + (size_t)krow * HID + c * 8);
    }
}

__global__ __launch_bounds__(256, 1)
void fused_head_gemm(const float* __restrict__ b1, const float* __restrict__ W2) {
    uint32_t smem_base = smem_u32(dynsmem);
    const int tid  = threadIdx.x;
    const int wid  = tid >> 5;
    const int lane = tid & 31;
    const int warp_m = wid & 1;     // 2 warps in M (64 rows each)
    const int warp_n = wid >> 1;    // 4 warps in N (64 cols each)
    const int g = lane >> 2;
    const int t = lane & 3;

    const int m0 = blockIdx.x * BM;
    const int n0 = blockIdx.y * BN;
    const int a  = blockIdx.z;

    const __nv_bfloat16* xA = g_xb  + (size_t)m0 * IN_DIM;
    const __nv_bfloat16* wB = g_w1b + (size_t)a * IN_DIM * HID + n0;

    {   // bias / W2 tile to smem
        float* b1s = (float*)(dynsmem + OFF_B1S);
        float* w2s = (float*)(dynsmem + OFF_W2S);
        b1s[tid] = b1[a * HID + n0 + tid];
        w2s[tid] = W2[a * HID + n0 + tid];
    }

    // ---- lane constants for fragment loads ----
    const int arow = lane & 15;
    const int ahi  = lane >> 4;
    const int asw  = arow & 7;
    // B (trans from [k][n]): krow_l in 16-k block, nc_l selects n-halves
    const int krow_l = (((lane >> 3) & 1) << 3) + (lane & 7);
    const int nc_l   = lane >> 4;
    const int bxor   = krow_l & 7;

    uint32_t a_rowbase[4];
    #pragma unroll
    for (int fm = 0; fm < 4; fm++)
        a_rowbase[fm] = (uint32_t)((warp_m * 64 + fm * 16 + arow) << 7);
    uint32_t b_coloff[4];
    #pragma unroll
    for (int p = 0; p < 4; p++)
        b_coloff[p] = (uint32_t)((((warp_n * 8 + p * 2 + nc_l) ^ bxor)) << 4);

    float acc[4][8][4];
    #pragma unroll
    for (int fm = 0; fm < 4; fm++)
        #pragma unroll
        for (int fn = 0; fn < 8; fn++)
            #pragma unroll
            for (int r = 0; r < 4; r++) acc[fm][fn][r] = 0.0f;

    // prologue: stages 0,1
    #pragma unroll
    for (int s = 0; s < NSTG - 1; s++) {
        #pragma unroll
        for (int part = 0; part < 4; part++) load_part(smem_base, s, s, part, xA, wB, tid);
        CP_COMMIT();
    }

    uint32_t Af[2][4][4], Bf[2][4][4];

    for (int kc = 0; kc < NC; ++kc) {
        if (kc == NC - 1) { CP_WAIT(0); } else { CP_WAIT(1); }
        __syncthreads();
        const uint32_t abase = smem_base + A_OFF(kc % NSTG);
        const uint32_t bbase = smem_base + B_OFF(kc % NSTG);
        const int pf = (kc + 2 < NC);
        const int pfs = (kc + 2) % NSTG;

        // load ks=0 fragments
        #pragma unroll
        for (int fm = 0; fm < 4; fm++)
            ldsm4(Af[0][fm], abase + a_rowbase[fm] + ((ahi ^ asw) << 4));
        #pragma unroll
        for (int p = 0; p < 4; p++)
            ldsm4t(Bf[0][p], bbase + (uint32_t)(krow_l * 512) + b_coloff[p]);

        #pragma unroll
        for (int ks = 0; ks < 4; ks++) {
            const int cur = ks & 1, nxt = cur ^ 1;
            if (ks < 3) {
                #pragma unroll
                for (int fm = 0; fm < 4; fm++)
                    ldsm4(Af[nxt][fm], abase + a_rowbase[fm] + ((((ks + 1) * 2 + ahi) ^ asw) << 4));
                #pragma unroll
                for (int p = 0; p < 4; p++)
                    ldsm4t(Bf[nxt][p], bbase + (uint32_t)(((ks + 1) * 16 + krow_l) * 512) + b_coloff[p]);
            }
            if (pf) load_part(smem_base, kc + 2, pfs, ks, xA, wB, tid);
            #pragma unroll
            for (int fm = 0; fm < 4; fm++)
                #pragma unroll
                for (int p = 0; p < 4; p++) {
                    mma16816(acc[fm][2 * p],     Af[cur][fm], Bf[cur][p][0], Bf[cur][p][1]);
                    mma16816(acc[fm][2 * p + 1], Af[cur][fm], Bf[cur][p][2], Bf[cur][p][3]);
                }
        }
        if (pf) CP_COMMIT();
    }

    // ---- epilogue ----
    const float* b1s = (const float*)(dynsmem + OFF_B1S);
    const float* w2s = (const float*)(dynsmem + OFF_W2S);
    float* red = (float*)(dynsmem + OFF_RED);   // [128][4]

    float pr[8];
    #pragma unroll
    for (int i = 0; i < 8; i++) pr[i] = 0.0f;

    #pragma unroll
    for (int fm = 0; fm < 4; fm++) {
        #pragma unroll
        for (int fn = 0; fn < 8; fn++) {
            int cbase = warp_n * 64 + fn * 8 + 2 * t;
            #pragma unroll
            for (int cc = 0; cc < 2; cc++) {
                int col = cbase + cc;
                float bb = b1s[col];
                float w2 = w2s[col];
                float v0 = acc[fm][fn][cc]     + bb;
                float v1 = acc[fm][fn][cc + 2] + bb;
                float h0 = 0.5f * v0 * (1.0f + erff(v0 * 0.70710678118654752f));
                float h1 = 0.5f * v1 * (1.0f + erff(v1 * 0.70710678118654752f));
                pr[fm * 2 + 0] += h0 * w2;
                pr[fm * 2 + 1] += h1 * w2;
            }
        }
    }
    #pragma unroll
    for (int i = 0; i < 8; i++) {
        pr[i] += __shfl_xor_sync(0xffffffffu, pr[i], 1);
        pr[i] += __shfl_xor_sync(0xffffffffu, pr[i], 2);
    }
    __syncthreads();
    if (t == 0) {
        #pragma unroll
        for (int i = 0; i < 8; i++) {
            int row = warp_m * 64 + (i >> 1) * 16 + (i & 1) * 8 + g;
            red[row * 4 + warp_n] = pr[i];
        }
    }
    __syncthreads();
    if (tid < BM) {
        float sum = red[tid * 4 + 0] + red[tid * 4 + 1] + red[tid * 4 + 2] + red[tid * 4 + 3];
        g_ypart[((size_t)(m0 + tid) * ATT_NUM + a) * NTILES + blockIdx.y] = sum;
    }
}

__global__ void finalize_kernel(const float* __restrict__ b2, float* __restrict__ out) {
    int i = blockIdx.x * blockDim.x + threadIdx.x;
    if (i >= BATCH * ATT_NUM) return;
    int a = i % ATT_NUM;
    float s = 0.0f;
    #pragma unroll
    for (int j = 0; j < NTILES; j++) s += g_ypart[(size_t)i * NTILES + j];
    s += b2[a];
    out[i] = 1.0f / (1.0f + expf(-s));
}

extern "C" void kernel_launch(void* const* d_in, const int* in_sizes, int n_in,
                              void* d_out, int out_size) {
    const float* x  = (const float*)d_in[0];
    const float* W1 = (const float*)d_in[1];
    const float* b1 = (const float*)d_in[2];
    const float* W2 = (const float*)d_in[3];
    const float* b2 = (const float*)d_in[4];
    float* out = (float*)d_out;

    cudaFuncSetAttribute(fused_head_gemm, cudaFuncAttributeMaxDynamicSharedMemorySize, SMEM_TOTAL);

    convert_x_kernel<<<(BATCH * IN_DIM / 4) / 256, 256>>>(x);
    {
        size_t n4 = (size_t)ATT_NUM * IN_DIM * HID / 4;
        convert_w1_kernel<<<(unsigned)(n4 / 256), 256>>>(W1);
    }

    dim3 grid(BATCH / BM, HID / BN, ATT_NUM);   // (32, 4, 40); x fastest -> W1 strip reuse in-wave
    fused_head_gemm<<<grid, 256, SMEM_TOTAL>>>(b1, W2);

    int n = BATCH * ATT_NUM;
    finalize_kernel<<<(n + 255) / 256, 256>>>(b2, out);
}